// round 2
// baseline (speedup 1.0000x reference)
#include <cuda_runtime.h>
#include <cuda_fp16.h>
#include <cstdint>

// ---------------- problem constants ----------------
#define TOKENS 8192
#define DIN    4096
#define DOUT   4096

// ---------------- GEMM tiling ----------------
#define BM 128
#define BN 256
#define BK 64                  // fp16 elements per K stage (128B of data per row)
#define STAGES 3
#define NKT (DIN / BK)         // 64 K iterations

// SMEM row stride: 128B data + 16B pad = 144B. Row spacing = 36 banks = 4 mod 32,
// so the 8 rows of one ldmatrix 8x8 hit 8 disjoint 4-bank groups: conflict-free.
#define STRIDE 144
#define A_OFF 0
#define A_BYTES (BM * STRIDE)            // 18432
#define B_OFF A_BYTES
#define B_BYTES (BN * STRIDE)            // 36864
#define STAGE_BYTES (A_BYTES + B_BYTES)  // 55296
#define SMEM_BYTES (STAGES * STAGE_BYTES)// 165888

// ---------------- device scratch (allocation-free rule: __device__ globals) ----------------
__device__ __half g_w[(size_t)DOUT   * DIN];   // 32 MB; codes 0..126 are EXACT in fp16
__device__ __half g_x[(size_t)TOKENS * DIN];   // 64 MB; rel err <= 2^-11 per element

// ---------------- PTX helpers (base-arch only: cp.async, ldmatrix, mma.sync) ----------------
__device__ __forceinline__ uint32_t smem_u32(const void* p) {
    return (uint32_t)__cvta_generic_to_shared(p);
}

__device__ __forceinline__ void cp16(uint32_t s, const void* g) {
    asm volatile("cp.async.cg.shared.global [%0], [%1], 16;" :: "r"(s), "l"(g));
}
__device__ __forceinline__ void cp_commit() {
    asm volatile("cp.async.commit_group;" ::: "memory");
}
template <int N>
__device__ __forceinline__ void cp_wait() {
    asm volatile("cp.async.wait_group %0;" :: "n"(N) : "memory");
}

__device__ __forceinline__ void ldsm4(uint32_t* r, uint32_t addr) {
    asm volatile("ldmatrix.sync.aligned.m8n8.x4.shared.b16 {%0,%1,%2,%3}, [%4];"
                 : "=r"(r[0]), "=r"(r[1]), "=r"(r[2]), "=r"(r[3]) : "r"(addr));
}

__device__ __forceinline__ void mma16816(float* d, const uint32_t* a, const uint32_t* b) {
    asm volatile(
        "mma.sync.aligned.m16n8k16.row.col.f32.f16.f16.f32 "
        "{%0,%1,%2,%3}, {%4,%5,%6,%7}, {%8,%9}, {%0,%1,%2,%3};"
        : "+f"(d[0]), "+f"(d[1]), "+f"(d[2]), "+f"(d[3])
        : "r"(a[0]), "r"(a[1]), "r"(a[2]), "r"(a[3]), "r"(b[0]), "r"(b[1]));
}

// ---------------- conversion kernels ----------------
__global__ void convert_x_kernel(const float4* __restrict__ x) {
    int i = blockIdx.x * blockDim.x + threadIdx.x;   // grid sized exactly
    float4 v = x[i];
    __half2 p0 = __floats2half2_rn(v.x, v.y);
    __half2 p1 = __floats2half2_rn(v.z, v.w);
    reinterpret_cast<__half2*>(g_x)[2 * i + 0] = p0;
    reinterpret_cast<__half2*>(g_x)[2 * i + 1] = p1;
}

__global__ void convert_w_kernel(const float4* __restrict__ w) {
    int i = blockIdx.x * blockDim.x + threadIdx.x;
    float4 v = w[i];
    __half2 p0 = __floats2half2_rn(v.x, v.y);   // exact: integer codes 0..126
    __half2 p1 = __floats2half2_rn(v.z, v.w);
    reinterpret_cast<__half2*>(g_w)[2 * i + 0] = p0;
    reinterpret_cast<__half2*>(g_w)[2 * i + 1] = p1;
}

// ---------------- stage loader ----------------
__device__ __forceinline__ void load_stage(uint32_t st, int gm0, int gn0, int k0, int tid) {
    // A: 128 rows x 8 segs of 16B = 1024 chunks (4 per thread)
#pragma unroll
    for (int t = 0; t < 4; t++) {
        int c = tid + t * 256;
        int row = c >> 3, seg = c & 7;
        cp16(st + A_OFF + row * STRIDE + seg * 16,
             g_x + (size_t)(gm0 + row) * DIN + k0 + seg * 8);
    }
    // B: 256 rows x 8 segs = 2048 chunks (8 per thread)
#pragma unroll
    for (int t = 0; t < 8; t++) {
        int c = tid + t * 256;
        int row = c >> 3, seg = c & 7;
        cp16(st + B_OFF + row * STRIDE + seg * 16,
             g_w + (size_t)(gn0 + row) * DIN + k0 + seg * 8);
    }
    cp_commit();
}

// ---------------- main GEMM ----------------
__global__ void __launch_bounds__(256, 1)
gemm_kernel(const float* __restrict__ bias, const float* __restrict__ scale,
            float* __restrict__ out) {
    extern __shared__ char dsm[];
    const uint32_t base = smem_u32(dsm);

    const int tid  = threadIdx.x;
    const int lane = tid & 31;
    const int wrp  = tid >> 5;                 // 8 warps: 2 (m) x 4 (n)
    const int wm   = (wrp & 1) * 64;           // warp m offset in tile
    const int wn   = (wrp >> 1) * 64;          // warp n offset in tile
    const int gn0  = blockIdx.x * BN;
    const int gm0  = blockIdx.y * BM;

    // lane-invariant ldmatrix address pieces: addr = base + (row0 + lane%16)*STRIDE
    //                                               + ks*32 + (lane/16)*16
    const int lrow = lane & 15;
    const int lcol = (lane >> 4) * 16;

    float acc[4][8][4];
#pragma unroll
    for (int mi = 0; mi < 4; mi++)
#pragma unroll
        for (int ni = 0; ni < 8; ni++)
#pragma unroll
            for (int c = 0; c < 4; c++) acc[mi][ni][c] = 0.0f;

    // prologue: fill STAGES-1 stages
    load_stage(base + 0 * STAGE_BYTES, gm0, gn0, 0 * BK, tid);
    load_stage(base + 1 * STAGE_BYTES, gm0, gn0, 1 * BK, tid);

    for (int kt = 0; kt < NKT; kt++) {
        const uint32_t st = base + (kt % STAGES) * STAGE_BYTES;

        if (kt < NKT - 1) cp_wait<1>(); else cp_wait<0>();
        __syncthreads();

        const int next = kt + 2;
        if (next < NKT)
            load_stage(base + (next % STAGES) * STAGE_BYTES, gm0, gn0, next * BK, tid);

        const uint32_t a_base = st + A_OFF + (wm + lrow) * STRIDE + lcol;
        const uint32_t b_base = st + B_OFF + (wn + lrow) * STRIDE + lcol;

#pragma unroll
        for (int ks = 0; ks < 4; ks++) {            // four k16 sub-steps per 64-K stage
            uint32_t a[4][4];
#pragma unroll
            for (int mi = 0; mi < 4; mi++)
                ldsm4(a[mi], a_base + mi * 16 * STRIDE + ks * 32);

            uint32_t b[8][2];
#pragma unroll
            for (int bi = 0; bi < 4; bi++) {        // each x4 covers n16 x k16
                uint32_t t4[4];
                ldsm4(t4, b_base + bi * 16 * STRIDE + ks * 32);
                b[2 * bi + 0][0] = t4[0]; b[2 * bi + 0][1] = t4[2];
                b[2 * bi + 1][0] = t4[1]; b[2 * bi + 1][1] = t4[3];
            }

#pragma unroll
            for (int mi = 0; mi < 4; mi++)
#pragma unroll
                for (int ni = 0; ni < 8; ni++)
                    mma16816(acc[mi][ni], a[mi], b[ni]);
        }
    }

    // ---------------- epilogue: y = acc * scale + bias ----------------
    const float sc = __ldg(scale);
    const int r0 = lane >> 2;           // row within m16
    const int c0 = 2 * (lane & 3);      // col within n8

#pragma unroll
    for (int ni = 0; ni < 8; ni++) {
        const int col = gn0 + wn + ni * 8 + c0;
        const float2 bv = *reinterpret_cast<const float2*>(bias + col);
#pragma unroll
        for (int mi = 0; mi < 4; mi++) {
            const int row = gm0 + wm + mi * 16 + r0;
            float2 o0, o1;
            o0.x = acc[mi][ni][0] * sc + bv.x;
            o0.y = acc[mi][ni][1] * sc + bv.y;
            o1.x = acc[mi][ni][2] * sc + bv.x;
            o1.y = acc[mi][ni][3] * sc + bv.y;
            *reinterpret_cast<float2*>(out + (size_t)row * DOUT + col)       = o0;
            *reinterpret_cast<float2*>(out + (size_t)(row + 8) * DOUT + col) = o1;
        }
    }
}

// ---------------- launch ----------------
extern "C" void kernel_launch(void* const* d_in, const int* in_sizes, int n_in,
                              void* d_out, int out_size) {
    const float* x     = (const float*)d_in[0];
    const float* w     = (const float*)d_in[1];
    const float* bias  = (const float*)d_in[2];
    const float* scale = (const float*)d_in[3];
    float* out = (float*)d_out;

    convert_x_kernel<<<32768, 256>>>((const float4*)x);   // 8192*4096/4/256
    convert_w_kernel<<<16384, 256>>>((const float4*)w);   // 4096*4096/4/256

    cudaFuncSetAttribute(gemm_kernel, cudaFuncAttributeMaxDynamicSharedMemorySize, SMEM_BYTES);
    dim3 grid(DOUT / BN, TOKENS / BM);   // (16, 64), x-fastest: a wave shares an A band
    gemm_kernel<<<grid, 256, SMEM_BYTES>>>(bias, scale, out);
}

// round 3
// speedup vs baseline: 1.0338x; 1.0338x over previous
#include <cuda_runtime.h>
#include <cuda_fp16.h>
#include <cstdint>

// ---------------- problem constants ----------------
#define TOKENS 8192
#define DIN    4096
#define DOUT   4096

// ---------------- GEMM tiling ----------------
#define BM 256                 // CTA tile M
#define BN 128                 // CTA tile N
#define BK 64                  // fp16 elements per K stage (128B of data per row)
#define STAGES 4
#define NKT (DIN / BK)         // 64 K iterations
#define NTHREADS 512           // 16 warps: 4 (m) x 4 (n), warp tile 64x32

// SMEM row stride: 128B data + 16B pad = 144B. Row spacing = 36 banks = 4 mod 32,
// so the 8 rows of one ldmatrix 8x8 phase hit 8 disjoint 4-bank groups: conflict-free.
#define STRIDE 144
#define A_OFF 0
#define A_BYTES (BM * STRIDE)            // 36864
#define B_OFF A_BYTES
#define B_BYTES (BN * STRIDE)            // 18432
#define STAGE_BYTES (A_BYTES + B_BYTES)  // 55296
#define SMEM_BYTES (STAGES * STAGE_BYTES)// 221184

// ---------------- device scratch (allocation-free rule: __device__ globals) ----------------
__device__ __half g_w[(size_t)DOUT   * DIN];   // 32 MB; codes 0..126 are EXACT in fp16
__device__ __half g_x[(size_t)TOKENS * DIN];   // 64 MB; rel err <= 2^-11 per element

// ---------------- PTX helpers (base-arch only: cp.async, ldmatrix, mma.sync) ----------------
__device__ __forceinline__ uint32_t smem_u32(const void* p) {
    return (uint32_t)__cvta_generic_to_shared(p);
}

__device__ __forceinline__ void cp16(uint32_t s, const void* g) {
    asm volatile("cp.async.cg.shared.global [%0], [%1], 16;" :: "r"(s), "l"(g));
}
__device__ __forceinline__ void cp_commit() {
    asm volatile("cp.async.commit_group;" ::: "memory");
}
template <int N>
__device__ __forceinline__ void cp_wait() {
    asm volatile("cp.async.wait_group %0;" :: "n"(N) : "memory");
}

__device__ __forceinline__ void ldsm4(uint32_t* r, uint32_t addr) {
    asm volatile("ldmatrix.sync.aligned.m8n8.x4.shared.b16 {%0,%1,%2,%3}, [%4];"
                 : "=r"(r[0]), "=r"(r[1]), "=r"(r[2]), "=r"(r[3]) : "r"(addr));
}

__device__ __forceinline__ void mma16816(float* d, const uint32_t* a, const uint32_t* b) {
    asm volatile(
        "mma.sync.aligned.m16n8k16.row.col.f32.f16.f16.f32 "
        "{%0,%1,%2,%3}, {%4,%5,%6,%7}, {%8,%9}, {%0,%1,%2,%3};"
        : "+f"(d[0]), "+f"(d[1]), "+f"(d[2]), "+f"(d[3])
        : "r"(a[0]), "r"(a[1]), "r"(a[2]), "r"(a[3]), "r"(b[0]), "r"(b[1]));
}

// ---------------- fused conversion kernel ----------------
// x: 8388608 float4, w: 4194304 float4 -> one kernel so the ncu -s 5 capture
// lands on the GEMM (launch sequence becomes {conv, gemm} pairs).
#define XN4 (TOKENS * DIN / 4)
#define WN4 (DOUT * DIN / 4)

__global__ void convert_all_kernel(const float4* __restrict__ x,
                                   const float4* __restrict__ w) {
    int i = blockIdx.x * blockDim.x + threadIdx.x;
    if (i < XN4) {
        float4 v = x[i];
        reinterpret_cast<__half2*>(g_x)[2 * i + 0] = __floats2half2_rn(v.x, v.y);
        reinterpret_cast<__half2*>(g_x)[2 * i + 1] = __floats2half2_rn(v.z, v.w);
    } else {
        int j = i - XN4;
        float4 v = w[j];
        reinterpret_cast<__half2*>(g_w)[2 * j + 0] = __floats2half2_rn(v.x, v.y);
        reinterpret_cast<__half2*>(g_w)[2 * j + 1] = __floats2half2_rn(v.z, v.w);
    }
}

// ---------------- stage loader ----------------
__device__ __forceinline__ void load_stage(uint32_t st, int gm0, int gn0, int k0, int tid) {
    // A: 256 rows x 8 segs of 16B = 2048 chunks (4 per thread)
#pragma unroll
    for (int t = 0; t < 4; t++) {
        int c = tid + t * NTHREADS;
        int row = c >> 3, seg = c & 7;
        cp16(st + A_OFF + row * STRIDE + seg * 16,
             g_x + (size_t)(gm0 + row) * DIN + k0 + seg * 8);
    }
    // B: 128 rows x 8 segs = 1024 chunks (2 per thread)
#pragma unroll
    for (int t = 0; t < 2; t++) {
        int c = tid + t * NTHREADS;
        int row = c >> 3, seg = c & 7;
        cp16(st + B_OFF + row * STRIDE + seg * 16,
             g_w + (size_t)(gn0 + row) * DIN + k0 + seg * 8);
    }
    cp_commit();
}

// ---------------- main GEMM ----------------
__global__ void __launch_bounds__(NTHREADS, 1)
gemm_kernel(const float* __restrict__ bias, const float* __restrict__ scale,
            float* __restrict__ out) {
    extern __shared__ char dsm[];
    const uint32_t base = smem_u32(dsm);

    const int tid  = threadIdx.x;
    const int lane = tid & 31;
    const int wrp  = tid >> 5;                 // 16 warps: 4 (m) x 4 (n)
    const int wm   = (wrp >> 2) * 64;          // warp m offset in tile
    const int wn   = (wrp & 3) * 32;           // warp n offset in tile
    const int gn0  = blockIdx.x * BN;
    const int gm0  = blockIdx.y * BM;

    const int lrow = lane & 15;
    const int lcol = (lane >> 4) * 16;

    float acc[4][4][4];
#pragma unroll
    for (int mi = 0; mi < 4; mi++)
#pragma unroll
        for (int ni = 0; ni < 4; ni++)
#pragma unroll
            for (int c = 0; c < 4; c++) acc[mi][ni][c] = 0.0f;

    // prologue: fill STAGES-1 = 3 stages
    load_stage(base + 0 * STAGE_BYTES, gm0, gn0, 0 * BK, tid);
    load_stage(base + 1 * STAGE_BYTES, gm0, gn0, 1 * BK, tid);
    load_stage(base + 2 * STAGE_BYTES, gm0, gn0, 2 * BK, tid);

    for (int kt = 0; kt < NKT; kt++) {
        const uint32_t st = base + (kt & 3) * STAGE_BYTES;

        // committed groups at this point: kt+3 total (indices 0..kt+2);
        // wait_group<2> guarantees group kt (this stage) has retired.
        cp_wait<2>();
        __syncthreads();

        const int next = kt + 3;
        if (next < NKT)
            load_stage(base + (next & 3) * STAGE_BYTES, gm0, gn0, next * BK, tid);
        else
            cp_commit();   // dummy group keeps the wait<2> invariant uniform

        const uint32_t a_base = st + A_OFF + (wm + lrow) * STRIDE + lcol;
        const uint32_t b_base = st + B_OFF + (wn + lrow) * STRIDE + lcol;

#pragma unroll
        for (int ks = 0; ks < 4; ks++) {            // four k16 sub-steps per 64-K stage
            uint32_t a[4][4];
#pragma unroll
            for (int mi = 0; mi < 4; mi++)
                ldsm4(a[mi], a_base + mi * 16 * STRIDE + ks * 32);

            uint32_t b[4][2];
#pragma unroll
            for (int bi = 0; bi < 2; bi++) {        // each x4 covers n16 x k16
                uint32_t t4[4];
                ldsm4(t4, b_base + bi * 16 * STRIDE + ks * 32);
                b[2 * bi + 0][0] = t4[0]; b[2 * bi + 0][1] = t4[2];
                b[2 * bi + 1][0] = t4[1]; b[2 * bi + 1][1] = t4[3];
            }

#pragma unroll
            for (int mi = 0; mi < 4; mi++)
#pragma unroll
                for (int ni = 0; ni < 4; ni++)
                    mma16816(acc[mi][ni], a[mi], b[ni]);
        }
    }

    // ---------------- epilogue: y = acc * scale + bias ----------------
    const float sc = __ldg(scale);
    const int r0 = lane >> 2;           // row within m16
    const int c0 = 2 * (lane & 3);      // col within n8

#pragma unroll
    for (int ni = 0; ni < 4; ni++) {
        const int col = gn0 + wn + ni * 8 + c0;
        const float2 bv = *reinterpret_cast<const float2*>(bias + col);
#pragma unroll
        for (int mi = 0; mi < 4; mi++) {
            const int row = gm0 + wm + mi * 16 + r0;
            float2 o0, o1;
            o0.x = acc[mi][ni][0] * sc + bv.x;
            o0.y = acc[mi][ni][1] * sc + bv.y;
            o1.x = acc[mi][ni][2] * sc + bv.x;
            o1.y = acc[mi][ni][3] * sc + bv.y;
            *reinterpret_cast<float2*>(out + (size_t)row * DOUT + col)       = o0;
            *reinterpret_cast<float2*>(out + (size_t)(row + 8) * DOUT + col) = o1;
        }
    }
}

// ---------------- launch ----------------
extern "C" void kernel_launch(void* const* d_in, const int* in_sizes, int n_in,
                              void* d_out, int out_size) {
    const float* x     = (const float*)d_in[0];
    const float* w     = (const float*)d_in[1];
    const float* bias  = (const float*)d_in[2];
    const float* scale = (const float*)d_in[3];
    float* out = (float*)d_out;

    convert_all_kernel<<<(XN4 + WN4) / 256, 256>>>((const float4*)x, (const float4*)w);

    cudaFuncSetAttribute(gemm_kernel, cudaFuncAttributeMaxDynamicSharedMemorySize, SMEM_BYTES);
    dim3 grid(DOUT / BN, TOKENS / BM);   // (32, 32), x-fastest: a wave shares an A band
    gemm_kernel<<<grid, NTHREADS, SMEM_BYTES>>>(bias, scale, out);
}